// round 4
// baseline (speedup 1.0000x reference)
#include <cuda_runtime.h>
#include <math.h>

#define B_    128
#define T_    256
#define IN_   256
#define HID_  512
#define NG_   1536   // 3*HID
#define OUT_  64

// ---------------- scratch (static __device__, no allocation) ----------------
__device__ float g_xg[(size_t)B_ * T_ * NG_];
__device__ float g_h0[(size_t)B_ * T_ * HID_];
__device__ float g_h1[(size_t)B_ * T_ * HID_];
__device__ unsigned g_ctr[2];

// ---------------- packed f32x2 helpers (Blackwell FFMA2) --------------------
__device__ __forceinline__ unsigned long long fma2(unsigned long long a,
                                                   unsigned long long b,
                                                   unsigned long long c) {
    unsigned long long d;
    asm("fma.rn.f32x2 %0, %1, %2, %3;" : "=l"(d) : "l"(a), "l"(b), "l"(c));
    return d;
}
__device__ __forceinline__ unsigned long long add2(unsigned long long a,
                                                   unsigned long long b) {
    unsigned long long d;
    asm("add.rn.f32x2 %0, %1, %2;" : "=l"(d) : "l"(a), "l"(b));
    return d;
}
__device__ __forceinline__ unsigned long long pack2(float x, float y) {
    unsigned long long r;
    asm("mov.b64 %0, {%1, %2};" : "=l"(r) : "f"(x), "f"(y));
    return r;
}
__device__ __forceinline__ void unpack2(unsigned long long v, float& x, float& y) {
    asm("mov.b64 {%0, %1}, %2;" : "=f"(x), "=f"(y) : "l"(v));
}

// ============================================================================
// GEMM: out[M,N] = X[M,K] @ W[N,K]^T + bias[N]   (both K-major)
// 128x128x8 tile, 256 threads. A pre-duplicated into smem as (a,a) u64 pairs:
// inner loop = 6 LDS.128 + 32 FMA2 per kk (no pack2).
// ============================================================================
#define BM 128
#define BN 128
#define BK 8

__global__ __launch_bounds__(256, 2)
void gemm_bias(const float* __restrict__ X, const float* __restrict__ W,
               const float* __restrict__ bias, float* __restrict__ out,
               int M, int N, int K)
{
    __shared__ unsigned long long As2[BK][BM + 2];   // duplicated (a,a)
    __shared__ float Bs[BK][BN + 4];

    const int tid = threadIdx.x;
    const int tx  = tid & 15;
    const int ty  = tid >> 4;
    const int m0  = blockIdx.y * BM;
    const int n0  = blockIdx.x * BN;

    const int lr = tid >> 1;
    const int lc = (tid & 1) * 4;

    const float* Xp = X + (size_t)(m0 + lr) * K + lc;
    const float* Wp = W + (size_t)(n0 + lr) * K + lc;

    unsigned long long acc[8][4];
#pragma unroll
    for (int i = 0; i < 8; i++)
#pragma unroll
        for (int j = 0; j < 4; j++) acc[i][j] = 0ull;

    float4 pa = *(const float4*)Xp;
    float4 pb = *(const float4*)Wp;

    for (int k0 = 0; k0 < K; k0 += BK) {
        As2[lc + 0][lr] = pack2(pa.x, pa.x);
        As2[lc + 1][lr] = pack2(pa.y, pa.y);
        As2[lc + 2][lr] = pack2(pa.z, pa.z);
        As2[lc + 3][lr] = pack2(pa.w, pa.w);
        Bs[lc + 0][lr] = pb.x; Bs[lc + 1][lr] = pb.y;
        Bs[lc + 2][lr] = pb.z; Bs[lc + 3][lr] = pb.w;
        __syncthreads();

        if (k0 + BK < K) {
            pa = *(const float4*)(Xp + k0 + BK);
            pb = *(const float4*)(Wp + k0 + BK);
        }

#pragma unroll
        for (int kk = 0; kk < BK; kk++) {
            ulonglong2 a01 = *(const ulonglong2*)&As2[kk][ty * 8];
            ulonglong2 a23 = *(const ulonglong2*)&As2[kk][ty * 8 + 2];
            ulonglong2 a45 = *(const ulonglong2*)&As2[kk][ty * 8 + 4];
            ulonglong2 a67 = *(const ulonglong2*)&As2[kk][ty * 8 + 6];
            ulonglong2 b0 = *(const ulonglong2*)&Bs[kk][tx * 4];       // n pairs 0,1
            ulonglong2 b1 = *(const ulonglong2*)&Bs[kk][64 + tx * 4];  // n pairs 2,3
            unsigned long long a[8] = {a01.x, a01.y, a23.x, a23.y,
                                       a45.x, a45.y, a67.x, a67.y};
#pragma unroll
            for (int i = 0; i < 8; i++) {
                acc[i][0] = fma2(a[i], b0.x, acc[i][0]);
                acc[i][1] = fma2(a[i], b0.y, acc[i][1]);
                acc[i][2] = fma2(a[i], b1.x, acc[i][2]);
                acc[i][3] = fma2(a[i], b1.y, acc[i][3]);
            }
        }
        __syncthreads();
    }

    float4 bv0 = *(const float4*)(bias + n0 + tx * 4);
    float4 bv1 = *(const float4*)(bias + n0 + 64 + tx * 4);
#pragma unroll
    for (int i = 0; i < 8; i++) {
        int m = m0 + ty * 8 + i;
        float f0, f1, f2, f3;
        float4 o;
        unpack2(acc[i][0], f0, f1); unpack2(acc[i][1], f2, f3);
        o.x = f0 + bv0.x; o.y = f1 + bv0.y; o.z = f2 + bv0.z; o.w = f3 + bv0.w;
        *(float4*)(out + (size_t)m * N + n0 + tx * 4) = o;
        unpack2(acc[i][2], f0, f1); unpack2(acc[i][3], f2, f3);
        o.x = f0 + bv1.x; o.y = f1 + bv1.y; o.z = f2 + bv1.z; o.w = f3 + bv1.w;
        *(float4*)(out + (size_t)m * N + n0 + 64 + tx * 4) = o;
    }
}

// ============================================================================
// Persistent GRU recurrence. 128 CTAs = 32 unit-tiles (16 units) x 4 batch-tiles
// (32 rows). 256 threads = 4 k-quarters x 64 threads. Thread micro-tile:
// 4 batch rows (bg+8i) x 2 units (ug2, ug2+8) x 3 gates = 24 packed-k f32x2
// accumulators -> 48 FMA2 per 10 conflict-free LDS.128 per k4.
// ============================================================================
#define RBT 32               // batch rows per CTA
#define RUT 16               // hidden units per CTA
#define HP  516              // padded row stride (floats)
#define KS4 128              // k depth per quarter
#define RED_U64 (24 * 192)   // red[acc 24][thread 192]
#define REC_SMEM_BYTES ((RBT * HP + 48 * HP) * 4 + RED_U64 * 8)

__global__ __launch_bounds__(256)
void gru_rec(const float* __restrict__ xg,   // [B*T, 1536]
             const float* __restrict__ Whh,  // [1536, 512]
             const float* __restrict__ bhh,  // [1536]
             float* __restrict__ hseq,       // [B, T, 512]
             unsigned* __restrict__ ctr)
{
    extern __shared__ float sm[];
    float* h_s = sm;                                    // [RBT][HP]
    float* W_s = sm + RBT * HP;                         // [48][HP], row = g*16+u
    unsigned long long* red =
        (unsigned long long*)(sm + RBT * HP + 48 * HP); // [24][192]
    __shared__ float bh_s[48];

    const int tid = threadIdx.x;
    const int u0  = blockIdx.x * RUT;
    const int b0  = blockIdx.y * RBT;
    const unsigned nCTA = gridDim.x * gridDim.y;

    // preload W_hh rows (48 x 512) and b_hh
    for (int i = tid; i < 48 * (HID_ / 4); i += 256) {
        int rr = i >> 7;             // 0..47
        int c4 = i & 127;
        int g = rr >> 4, u = rr & 15;
        float4 v = *(const float4*)(Whh + (size_t)(g * HID_ + u0 + u) * HID_ + c4 * 4);
        *(float4*)&W_s[rr * HP + c4 * 4] = v;
    }
    if (tid < 48) {
        int g = tid >> 4, u = tid & 15;
        bh_s[tid] = bhh[g * HID_ + u0 + u];
    }

    const int ks  = tid >> 6;        // k-quarter 0..3
    const int r   = tid & 63;
    const int ug2 = r & 7;           // unit pair: units ug2, ug2+8
    const int bg  = r >> 3;          // 0..7 -> rows bg+8i
    const int kb  = ks * KS4;

    // conflict-free: unit step 1 -> bank step 4 across the 8 lanes per group
    const ulonglong2* wp[2][3];
#pragma unroll
    for (int j = 0; j < 2; j++)
#pragma unroll
        for (int g = 0; g < 3; g++)
            wp[j][g] = (const ulonglong2*)(W_s + (g * 16 + ug2 + 8 * j) * HP + kb);
    const ulonglong2* hA = (const ulonglong2*)(h_s + (bg +  0) * HP + kb);
    const ulonglong2* hB = (const ulonglong2*)(h_s + (bg +  8) * HP + kb);
    const ulonglong2* hC = (const ulonglong2*)(h_s + (bg + 16) * HP + kb);
    const ulonglong2* hD = (const ulonglong2*)(h_s + (bg + 24) * HP + kb);

    for (int t = 0; t < T_; t++) {
        // ---- stage previous h tile [32 x 512] into smem (cp.async) ----
        if (t == 0) {
            for (int i = tid; i < RBT * (HID_ / 4); i += 256)
                *(float4*)&h_s[(i >> 7) * HP + (i & 127) * 4] =
                    make_float4(0.f, 0.f, 0.f, 0.f);
        } else {
            for (int i = tid; i < RBT * (HID_ / 4); i += 256) {
                int rr = i >> 7, c4 = i & 127;
                const float* src = hseq + ((size_t)(b0 + rr) * T_ + (t - 1)) * HID_ + c4 * 4;
                unsigned sdst = (unsigned)__cvta_generic_to_shared(&h_s[rr * HP + c4 * 4]);
                asm volatile("cp.async.cg.shared.global [%0], [%1], 16;"
                             :: "r"(sdst), "l"(src));
            }
            asm volatile("cp.async.commit_group;");
        }

        // ---- xg prefetch (ks0 only), issued while cp.async is in flight ----
        float xv[2][3][4];   // [unit j][gate][batch i]
        if (ks == 0) {
#pragma unroll
            for (int i = 0; i < 4; i++) {
                size_t base = ((size_t)(b0 + bg + 8 * i) * T_ + t) * NG_ + u0;
#pragma unroll
                for (int j = 0; j < 2; j++) {
                    int u = ug2 + 8 * j;
                    xv[j][0][i] = __ldg(xg + base + u);
                    xv[j][1][i] = __ldg(xg + base + 512 + u);
                    xv[j][2][i] = __ldg(xg + base + 1024 + u);
                }
            }
        }

        if (t != 0) asm volatile("cp.async.wait_group 0;");
        __syncthreads();

        unsigned long long A[4][2][3];
#pragma unroll
        for (int i = 0; i < 4; i++)
#pragma unroll
            for (int j = 0; j < 2; j++)
#pragma unroll
                for (int g = 0; g < 3; g++) A[i][j][g] = 0ull;

#pragma unroll 4
        for (int k4 = 0; k4 < KS4 / 4; k4++) {
            ulonglong2 hv0 = hA[k4];
            ulonglong2 hv1 = hB[k4];
            ulonglong2 hv2 = hC[k4];
            ulonglong2 hv3 = hD[k4];
            ulonglong2 wv[2][3];
#pragma unroll
            for (int j = 0; j < 2; j++)
#pragma unroll
                for (int g = 0; g < 3; g++) wv[j][g] = wp[j][g][k4];

#pragma unroll
            for (int j = 0; j < 2; j++)
#pragma unroll
                for (int g = 0; g < 3; g++) {
                    A[0][j][g] = fma2(hv0.x, wv[j][g].x, A[0][j][g]);
                    A[0][j][g] = fma2(hv0.y, wv[j][g].y, A[0][j][g]);
                    A[1][j][g] = fma2(hv1.x, wv[j][g].x, A[1][j][g]);
                    A[1][j][g] = fma2(hv1.y, wv[j][g].y, A[1][j][g]);
                    A[2][j][g] = fma2(hv2.x, wv[j][g].x, A[2][j][g]);
                    A[2][j][g] = fma2(hv2.y, wv[j][g].y, A[2][j][g]);
                    A[3][j][g] = fma2(hv3.x, wv[j][g].x, A[3][j][g]);
                    A[3][j][g] = fma2(hv3.y, wv[j][g].y, A[3][j][g]);
                }
        }

        // ---- cross-quarter reduction (transposed layout, conflict-free) ----
        if (ks != 0) {
            int col = (ks - 1) * 64 + r;
#pragma unroll
            for (int i = 0; i < 4; i++)
#pragma unroll
                for (int j = 0; j < 2; j++)
#pragma unroll
                    for (int g = 0; g < 3; g++)
                        red[((i * 2 + j) * 3 + g) * 192 + col] = A[i][j][g];
        }
        __syncthreads();

        if (ks == 0) {
#pragma unroll
            for (int i = 0; i < 4; i++)
#pragma unroll
                for (int j = 0; j < 2; j++)
#pragma unroll
                    for (int g = 0; g < 3; g++) {
                        const unsigned long long* rp =
                            red + ((i * 2 + j) * 3 + g) * 192 + r;
                        A[i][j][g] = add2(A[i][j][g], rp[0]);
                        A[i][j][g] = add2(A[i][j][g], rp[64]);
                        A[i][j][g] = add2(A[i][j][g], rp[128]);
                    }

#pragma unroll
            for (int j = 0; j < 2; j++) {
                int ul = ug2 + 8 * j;
                const float br = bh_s[ul], bz = bh_s[16 + ul], bn = bh_s[32 + ul];
#pragma unroll
                for (int i = 0; i < 4; i++) {
                    float lo, hi;
                    unpack2(A[i][j][0], lo, hi); float hr = lo + hi + br;
                    unpack2(A[i][j][1], lo, hi); float hz = lo + hi + bz;
                    unpack2(A[i][j][2], lo, hi); float hn = lo + hi + bn;
                    float rr = 1.f / (1.f + __expf(-(xv[j][0][i] + hr)));
                    float zz = 1.f / (1.f + __expf(-(xv[j][1][i] + hz)));
                    float nn = tanhf(xv[j][2][i] + rr * hn);
                    float hp = h_s[(bg + 8 * i) * HP + u0 + ul];
                    int b = b0 + bg + 8 * i;
                    hseq[((size_t)b * T_ + t) * HID_ + u0 + ul] =
                        (1.f - zz) * nn + zz * hp;
                }
            }
        }
        __syncthreads();   // all reads of h_s / red complete

        if (t < T_ - 1) {
            if (tid == 0) {
                __threadfence();
                atomicAdd(ctr, 1u);
                unsigned target = (unsigned)(t + 1) * nCTA;
                volatile unsigned* vc = ctr;
                while (*vc < target) { }
                __threadfence();
            }
            __syncthreads();
        }
    }
}

// ============================================================================
// Head
// ============================================================================
__global__ __launch_bounds__(64)
void out_proj(const float* __restrict__ hseq, const float* __restrict__ Wout,
              const float* __restrict__ bout, float* __restrict__ y)
{
    __shared__ float hs[HID_];
    const int b = blockIdx.x;
    const float* h = hseq + ((size_t)b * T_ + (T_ - 1)) * HID_;
    for (int i = threadIdx.x; i < HID_; i += 64) hs[i] = h[i];
    __syncthreads();

    const int o = threadIdx.x;
    float acc = bout[o];
    const float* w = Wout + (size_t)o * HID_;
#pragma unroll 4
    for (int k = 0; k < HID_; k += 4) {
        float4 wv = *(const float4*)(w + k);
        acc += hs[k] * wv.x + hs[k + 1] * wv.y + hs[k + 2] * wv.z + hs[k + 3] * wv.w;
    }
    y[b * OUT_ + o] = acc;
}

// ============================================================================
extern "C" void kernel_launch(void* const* d_in, const int* in_sizes, int n_in,
                              void* d_out, int out_size)
{
    (void)in_sizes; (void)n_in; (void)out_size;
    const float* x     = (const float*)d_in[0];
    const float* W_ih0 = (const float*)d_in[1];
    const float* W_hh0 = (const float*)d_in[2];
    const float* b_ih0 = (const float*)d_in[3];
    const float* b_hh0 = (const float*)d_in[4];
    const float* W_ih1 = (const float*)d_in[5];
    const float* W_hh1 = (const float*)d_in[6];
    const float* b_ih1 = (const float*)d_in[7];
    const float* b_hh1 = (const float*)d_in[8];
    const float* W_out = (const float*)d_in[9];
    const float* b_out = (const float*)d_in[10];
    float* y = (float*)d_out;

    float *xg, *h0, *h1;
    unsigned* ctr;
    cudaGetSymbolAddress((void**)&xg, g_xg);
    cudaGetSymbolAddress((void**)&h0, g_h0);
    cudaGetSymbolAddress((void**)&h1, g_h1);
    cudaGetSymbolAddress((void**)&ctr, g_ctr);

    cudaFuncSetAttribute(gru_rec, cudaFuncAttributeMaxDynamicSharedMemorySize,
                         REC_SMEM_BYTES);

    cudaMemsetAsync(ctr, 0, 2 * sizeof(unsigned));

    const dim3 ggrid(NG_ / BN, (B_ * T_) / BM);   // 12 x 256

    gemm_bias<<<ggrid, 256>>>(x, W_ih0, b_ih0, xg, B_ * T_, NG_, IN_);
    gru_rec<<<dim3(HID_ / RUT, B_ / RBT), 256, REC_SMEM_BYTES>>>(xg, W_hh0, b_hh0, h0, ctr);

    gemm_bias<<<ggrid, 256>>>(h0, W_ih1, b_ih1, xg, B_ * T_, NG_, HID_);
    gru_rec<<<dim3(HID_ / RUT, B_ / RBT), 256, REC_SMEM_BYTES>>>(xg, W_hh1, b_hh1, h1, ctr + 1);

    out_proj<<<B_, 64>>>(h1, W_out, b_out, y);
}

// round 5
// speedup vs baseline: 1.0169x; 1.0169x over previous
#include <cuda_runtime.h>
#include <math.h>

#define B_    128
#define T_    256
#define IN_   256
#define HID_  512
#define NG_   1536   // 3*HID
#define OUT_  64

// ---------------- scratch (static __device__, no allocation) ----------------
__device__ float g_xg[(size_t)B_ * T_ * NG_];
__device__ float g_h0[(size_t)B_ * T_ * HID_];
__device__ float g_h1[(size_t)B_ * T_ * HID_];
__device__ unsigned g_ctr[2 * 4 * 32];           // [layer][batch-domain][pad 128B]

// ---------------- packed f32x2 helpers --------------------------------------
__device__ __forceinline__ unsigned long long fma2(unsigned long long a,
                                                   unsigned long long b,
                                                   unsigned long long c) {
    unsigned long long d;
    asm("fma.rn.f32x2 %0, %1, %2, %3;" : "=l"(d) : "l"(a), "l"(b), "l"(c));
    return d;
}
__device__ __forceinline__ unsigned long long pack2(float x, float y) {
    unsigned long long r;
    asm("mov.b64 %0, {%1, %2};" : "=l"(r) : "f"(x), "f"(y));
    return r;
}
__device__ __forceinline__ void unpack2(unsigned long long v, float& x, float& y) {
    asm("mov.b64 {%0, %1}, %2;" : "=f"(x), "=f"(y) : "l"(v));
}
__device__ __forceinline__ float hadd2(unsigned long long v) {
    float x, y;
    asm("mov.b64 {%0, %1}, %2;" : "=f"(x), "=f"(y) : "l"(v));
    return x + y;
}

// ============================================================================
// GEMM: out[M,N] = X[M,K] @ W[N,K]^T + bias[N]   (R3 version — best run)
// ============================================================================
#define BM 128
#define BN 128
#define BK 8

__global__ __launch_bounds__(256, 2)
void gemm_bias(const float* __restrict__ X, const float* __restrict__ W,
               const float* __restrict__ bias, float* __restrict__ out,
               int M, int N, int K)
{
    __shared__ float As[BK][BM + 4];
    __shared__ float Bs[BK][BN + 4];

    const int tid = threadIdx.x;
    const int tx  = tid & 15;
    const int ty  = tid >> 4;
    const int m0  = blockIdx.y * BM;
    const int n0  = blockIdx.x * BN;

    const int lr = tid >> 1;
    const int lc = (tid & 1) * 4;

    const float* Xp = X + (size_t)(m0 + lr) * K + lc;
    const float* Wp = W + (size_t)(n0 + lr) * K + lc;

    unsigned long long acc[8][4];
#pragma unroll
    for (int i = 0; i < 8; i++)
#pragma unroll
        for (int j = 0; j < 4; j++) acc[i][j] = 0ull;

    float4 pa = *(const float4*)Xp;
    float4 pb = *(const float4*)Wp;

    for (int k0 = 0; k0 < K; k0 += BK) {
        As[lc + 0][lr] = pa.x; As[lc + 1][lr] = pa.y;
        As[lc + 2][lr] = pa.z; As[lc + 3][lr] = pa.w;
        Bs[lc + 0][lr] = pb.x; Bs[lc + 1][lr] = pb.y;
        Bs[lc + 2][lr] = pb.z; Bs[lc + 3][lr] = pb.w;
        __syncthreads();

        if (k0 + BK < K) {
            pa = *(const float4*)(Xp + k0 + BK);
            pb = *(const float4*)(Wp + k0 + BK);
        }

#pragma unroll
        for (int kk = 0; kk < BK; kk++) {
            float4 a0 = *(const float4*)&As[kk][ty * 8];
            float4 a1 = *(const float4*)&As[kk][ty * 8 + 4];
            ulonglong2 b0 = *(const ulonglong2*)&Bs[kk][tx * 4];
            ulonglong2 b1 = *(const ulonglong2*)&Bs[kk][64 + tx * 4];
            float a[8] = {a0.x, a0.y, a0.z, a0.w, a1.x, a1.y, a1.z, a1.w};
#pragma unroll
            for (int i = 0; i < 8; i++) {
                unsigned long long a2 = pack2(a[i], a[i]);
                acc[i][0] = fma2(a2, b0.x, acc[i][0]);
                acc[i][1] = fma2(a2, b0.y, acc[i][1]);
                acc[i][2] = fma2(a2, b1.x, acc[i][2]);
                acc[i][3] = fma2(a2, b1.y, acc[i][3]);
            }
        }
        __syncthreads();
    }

    float4 bv0 = *(const float4*)(bias + n0 + tx * 4);
    float4 bv1 = *(const float4*)(bias + n0 + 64 + tx * 4);
#pragma unroll
    for (int i = 0; i < 8; i++) {
        int m = m0 + ty * 8 + i;
        float f0, f1, f2, f3;
        float4 o;
        unpack2(acc[i][0], f0, f1); unpack2(acc[i][1], f2, f3);
        o.x = f0 + bv0.x; o.y = f1 + bv0.y; o.z = f2 + bv0.z; o.w = f3 + bv0.w;
        *(float4*)(out + (size_t)m * N + n0 + tx * 4) = o;
        unpack2(acc[i][2], f0, f1); unpack2(acc[i][3], f2, f3);
        o.x = f0 + bv1.x; o.y = f1 + bv1.y; o.z = f2 + bv1.z; o.w = f3 + bv1.w;
        *(float4*)(out + (size_t)m * N + n0 + 64 + tx * 4) = o;
    }
}

// ============================================================================
// Persistent GRU recurrence. 128 CTAs = 32 unit-tiles x 4 batch-tiles.
// Barrier is PER BATCH-TILE (32 CTAs, independent domains).
// 256 threads = 4 k-quarters x 64. Thread: 4 batch x 2 units x 3 gates.
// ============================================================================
#define RBT 32               // batch rows per CTA
#define RUT 16               // hidden units per CTA
#define HP  516              // padded row stride (floats)
#define KS4 128              // k depth per quarter
#define REC_SMEM_BYTES ((RBT * HP + 48 * HP + 24 * 192) * 4)

__global__ __launch_bounds__(256)
void gru_rec(const float* __restrict__ xg,   // [B*T, 1536]
             const float* __restrict__ Whh,  // [1536, 512]
             const float* __restrict__ bhh,  // [1536]
             float* __restrict__ hseq,       // [B, T, 512]
             unsigned* __restrict__ ctr)     // 4 domains x 32-uint pad
{
    extern __shared__ float sm[];
    float* h_s  = sm;                         // [RBT][HP]
    float* W_s  = sm + RBT * HP;              // [48][HP], row = g*16+u
    float* redf = sm + RBT * HP + 48 * HP;    // [24][192] scalar partials
    __shared__ float bh_s[48];

    const int tid = threadIdx.x;
    const int u0  = blockIdx.x * RUT;
    const int b0  = blockIdx.y * RBT;
    unsigned* cnt = ctr + blockIdx.y * 32;    // this batch-domain's counter
    const unsigned nDOM = gridDim.x;          // 32 CTAs per domain

    // preload W_hh rows (48 x 512) and b_hh
    for (int i = tid; i < 48 * (HID_ / 4); i += 256) {
        int rr = i >> 7;
        int c4 = i & 127;
        int g = rr >> 4, u = rr & 15;
        float4 v = *(const float4*)(Whh + (size_t)(g * HID_ + u0 + u) * HID_ + c4 * 4);
        *(float4*)&W_s[rr * HP + c4 * 4] = v;
    }
    if (tid < 48) {
        int g = tid >> 4, u = tid & 15;
        bh_s[tid] = bhh[g * HID_ + u0 + u];
    }

    const int ks  = tid >> 6;        // k-quarter 0..3
    const int r   = tid & 63;
    const int ug2 = r & 7;           // unit pair: units ug2, ug2+8
    const int bg  = r >> 3;          // 0..7 -> rows bg+8i
    const int kb  = ks * KS4;

    const ulonglong2* wp[2][3];
#pragma unroll
    for (int j = 0; j < 2; j++)
#pragma unroll
        for (int g = 0; g < 3; g++)
            wp[j][g] = (const ulonglong2*)(W_s + (g * 16 + ug2 + 8 * j) * HP + kb);
    const ulonglong2* hA = (const ulonglong2*)(h_s + (bg +  0) * HP + kb);
    const ulonglong2* hB = (const ulonglong2*)(h_s + (bg +  8) * HP + kb);
    const ulonglong2* hC = (const ulonglong2*)(h_s + (bg + 16) * HP + kb);
    const ulonglong2* hD = (const ulonglong2*)(h_s + (bg + 24) * HP + kb);

    for (int t = 0; t < T_; t++) {
        // ---- stage previous h tile [32 x 512] into smem (cp.async) ----
        if (t == 0) {
            for (int i = tid; i < RBT * (HID_ / 4); i += 256)
                *(float4*)&h_s[(i >> 7) * HP + (i & 127) * 4] =
                    make_float4(0.f, 0.f, 0.f, 0.f);
        } else {
            for (int i = tid; i < RBT * (HID_ / 4); i += 256) {
                int rr = i >> 7, c4 = i & 127;
                const float* src = hseq + ((size_t)(b0 + rr) * T_ + (t - 1)) * HID_ + c4 * 4;
                unsigned sdst = (unsigned)__cvta_generic_to_shared(&h_s[rr * HP + c4 * 4]);
                asm volatile("cp.async.cg.shared.global [%0], [%1], 16;"
                             :: "r"(sdst), "l"(src));
            }
            asm volatile("cp.async.commit_group;");
        }

        // ---- xg prefetch (ks0 only), overlapped with cp.async ----
        float xv[2][3][4];
        if (ks == 0) {
#pragma unroll
            for (int i = 0; i < 4; i++) {
                size_t base = ((size_t)(b0 + bg + 8 * i) * T_ + t) * NG_ + u0;
#pragma unroll
                for (int j = 0; j < 2; j++) {
                    int u = ug2 + 8 * j;
                    xv[j][0][i] = __ldg(xg + base + u);
                    xv[j][1][i] = __ldg(xg + base + 512 + u);
                    xv[j][2][i] = __ldg(xg + base + 1024 + u);
                }
            }
        }

        if (t != 0) asm volatile("cp.async.wait_group 0;");
        __syncthreads();

        unsigned long long A[4][2][3];
#pragma unroll
        for (int i = 0; i < 4; i++)
#pragma unroll
            for (int j = 0; j < 2; j++)
#pragma unroll
                for (int g = 0; g < 3; g++) A[i][j][g] = 0ull;

#pragma unroll 2
        for (int k4 = 0; k4 < KS4 / 4; k4++) {
            ulonglong2 hv0 = hA[k4];
            ulonglong2 hv1 = hB[k4];
            ulonglong2 hv2 = hC[k4];
            ulonglong2 hv3 = hD[k4];
            ulonglong2 wv[2][3];
#pragma unroll
            for (int j = 0; j < 2; j++)
#pragma unroll
                for (int g = 0; g < 3; g++) wv[j][g] = wp[j][g][k4];

#pragma unroll
            for (int j = 0; j < 2; j++)
#pragma unroll
                for (int g = 0; g < 3; g++) {
                    A[0][j][g] = fma2(hv0.x, wv[j][g].x, A[0][j][g]);
                    A[0][j][g] = fma2(hv0.y, wv[j][g].y, A[0][j][g]);
                    A[1][j][g] = fma2(hv1.x, wv[j][g].x, A[1][j][g]);
                    A[1][j][g] = fma2(hv1.y, wv[j][g].y, A[1][j][g]);
                    A[2][j][g] = fma2(hv2.x, wv[j][g].x, A[2][j][g]);
                    A[2][j][g] = fma2(hv2.y, wv[j][g].y, A[2][j][g]);
                    A[3][j][g] = fma2(hv3.x, wv[j][g].x, A[3][j][g]);
                    A[3][j][g] = fma2(hv3.y, wv[j][g].y, A[3][j][g]);
                }
        }

        // ---- cross-quarter reduction: horizontal add -> scalar partials ----
        if (ks != 0) {
            int col = (ks - 1) * 64 + r;
#pragma unroll
            for (int i = 0; i < 4; i++)
#pragma unroll
                for (int j = 0; j < 2; j++)
#pragma unroll
                    for (int g = 0; g < 3; g++)
                        redf[((i * 2 + j) * 3 + g) * 192 + col] = hadd2(A[i][j][g]);
        }
        __syncthreads();

        if (ks == 0) {
#pragma unroll
            for (int j = 0; j < 2; j++) {
                int ul = ug2 + 8 * j;
                const float br = bh_s[ul], bz = bh_s[16 + ul], bn = bh_s[32 + ul];
#pragma unroll
                for (int i = 0; i < 4; i++) {
                    const float* r0 = redf + ((i * 2 + j) * 3 + 0) * 192 + r;
                    const float* r1 = redf + ((i * 2 + j) * 3 + 1) * 192 + r;
                    const float* r2 = redf + ((i * 2 + j) * 3 + 2) * 192 + r;
                    float hr = hadd2(A[i][j][0]) + r0[0] + r0[64] + r0[128] + br;
                    float hz = hadd2(A[i][j][1]) + r1[0] + r1[64] + r1[128] + bz;
                    float hn = hadd2(A[i][j][2]) + r2[0] + r2[64] + r2[128] + bn;
                    float rr = 1.f / (1.f + __expf(-(xv[j][0][i] + hr)));
                    float zz = 1.f / (1.f + __expf(-(xv[j][1][i] + hz)));
                    float nn = tanhf(xv[j][2][i] + rr * hn);
                    float hp = h_s[(bg + 8 * i) * HP + u0 + ul];
                    int b = b0 + bg + 8 * i;
                    hseq[((size_t)b * T_ + t) * HID_ + u0 + ul] =
                        (1.f - zz) * nn + zz * hp;
                }
            }
        }

        // ---- early arrival: epilogue warps (0-1) sync, tid0 releases ----
        if (t < T_ - 1) {
            if (tid < 64) {
                asm volatile("bar.sync 1, 64;" ::: "memory");
                if (tid == 0)
                    asm volatile("red.release.gpu.global.add.u32 [%0], %1;"
                                 :: "l"(cnt), "r"(1u) : "memory");
            }
            __syncthreads();          // all h_s / redf reads complete
            if (tid == 0) {
                unsigned target = (unsigned)(t + 1) * nDOM;
                unsigned v;
                do {
                    asm volatile("ld.acquire.gpu.global.u32 %0, [%1];"
                                 : "=r"(v) : "l"(cnt) : "memory");
                } while (v < target);
            }
            __syncthreads();
        }
    }
}

// ============================================================================
// Head
// ============================================================================
__global__ __launch_bounds__(64)
void out_proj(const float* __restrict__ hseq, const float* __restrict__ Wout,
              const float* __restrict__ bout, float* __restrict__ y)
{
    __shared__ float hs[HID_];
    const int b = blockIdx.x;
    const float* h = hseq + ((size_t)b * T_ + (T_ - 1)) * HID_;
    for (int i = threadIdx.x; i < HID_; i += 64) hs[i] = h[i];
    __syncthreads();

    const int o = threadIdx.x;
    float acc = bout[o];
    const float* w = Wout + (size_t)o * HID_;
#pragma unroll 4
    for (int k = 0; k < HID_; k += 4) {
        float4 wv = *(const float4*)(w + k);
        acc += hs[k] * wv.x + hs[k + 1] * wv.y + hs[k + 2] * wv.z + hs[k + 3] * wv.w;
    }
    y[b * OUT_ + o] = acc;
}

// ============================================================================
extern "C" void kernel_launch(void* const* d_in, const int* in_sizes, int n_in,
                              void* d_out, int out_size)
{
    (void)in_sizes; (void)n_in; (void)out_size;
    const float* x     = (const float*)d_in[0];
    const float* W_ih0 = (const float*)d_in[1];
    const float* W_hh0 = (const float*)d_in[2];
    const float* b_ih0 = (const float*)d_in[3];
    const float* b_hh0 = (const float*)d_in[4];
    const float* W_ih1 = (const float*)d_in[5];
    const float* W_hh1 = (const float*)d_in[6];
    const float* b_ih1 = (const float*)d_in[7];
    const float* b_hh1 = (const float*)d_in[8];
    const float* W_out = (const float*)d_in[9];
    const float* b_out = (const float*)d_in[10];
    float* y = (float*)d_out;

    float *xg, *h0, *h1;
    unsigned* ctr;
    cudaGetSymbolAddress((void**)&xg, g_xg);
    cudaGetSymbolAddress((void**)&h0, g_h0);
    cudaGetSymbolAddress((void**)&h1, g_h1);
    cudaGetSymbolAddress((void**)&ctr, g_ctr);

    cudaFuncSetAttribute(gru_rec, cudaFuncAttributeMaxDynamicSharedMemorySize,
                         REC_SMEM_BYTES);

    cudaMemsetAsync(ctr, 0, 2 * 4 * 32 * sizeof(unsigned));

    const dim3 ggrid(NG_ / BN, (B_ * T_) / BM);   // 12 x 256

    gemm_bias<<<ggrid, 256>>>(x, W_ih0, b_ih0, xg, B_ * T_, NG_, IN_);
    gru_rec<<<dim3(HID_ / RUT, B_ / RBT), 256, REC_SMEM_BYTES>>>(xg, W_hh0, b_hh0, h0, ctr);

    gemm_bias<<<ggrid, 256>>>(h0, W_ih1, b_ih1, xg, B_ * T_, NG_, HID_);
    gru_rec<<<dim3(HID_ / RUT, B_ / RBT), 256, REC_SMEM_BYTES>>>(xg, W_hh1, b_hh1, h1, ctr + 4 * 32);

    out_proj<<<B_, 64>>>(h1, W_out, b_out, y);
}

// round 6
// speedup vs baseline: 1.1785x; 1.1590x over previous
#include <cuda_runtime.h>
#include <math.h>

#define B_    128
#define T_    256
#define IN_   256
#define HID_  512
#define NG_   1536   // 3*HID
#define OUT_  64

// ---------------- scratch (static __device__, no allocation) ----------------
__device__ float g_xg[(size_t)B_ * T_ * NG_];
__device__ float g_h0[(size_t)B_ * T_ * HID_];
__device__ float g_h1[(size_t)B_ * T_ * HID_];
__device__ unsigned g_ctr[2];

// ---------------- packed f32x2 helpers --------------------------------------
__device__ __forceinline__ unsigned long long fma2(unsigned long long a,
                                                   unsigned long long b,
                                                   unsigned long long c) {
    unsigned long long d;
    asm("fma.rn.f32x2 %0, %1, %2, %3;" : "=l"(d) : "l"(a), "l"(b), "l"(c));
    return d;
}
__device__ __forceinline__ unsigned long long add2(unsigned long long a,
                                                   unsigned long long b) {
    unsigned long long d;
    asm("add.rn.f32x2 %0, %1, %2;" : "=l"(d) : "l"(a), "l"(b));
    return d;
}
__device__ __forceinline__ void unpack2(unsigned long long v, float& x, float& y) {
    asm("mov.b64 {%0, %1}, %2;" : "=f"(x), "=f"(y) : "l"(v));
}
__device__ __forceinline__ unsigned f2tf32(float f) {
    unsigned u;
    asm("cvt.rna.tf32.f32 %0, %1;" : "=r"(u) : "f"(f));
    return u;
}

// ============================================================================
// tf32 tensor-core GEMM: out[M,N] = X[M,K] @ W[N,K]^T + bias[N]
// 128x128x32 tile, 256 threads = 8 warps (4m x 2n), warp tile 32x64.
// mma.sync.aligned.m16n8k8.row.col.f32.tf32.tf32.f32.
// fp32 -> tf32 conversion at smem staging (once per element).
// ============================================================================
#define BM 128
#define BN 128
#define BK 32
#define SP 36     // smem pitch: bank(frag) = 4g+tg, conflict-free

__global__ __launch_bounds__(256, 2)
void gemm_tf32(const float* __restrict__ X, const float* __restrict__ W,
               const float* __restrict__ bias, float* __restrict__ out,
               int M, int N, int K)
{
    __shared__ unsigned Xs[BM][SP];
    __shared__ unsigned Ws[BN][SP];

    const int tid  = threadIdx.x;
    const int lane = tid & 31;
    const int wid  = tid >> 5;
    const int g    = lane >> 2;      // 0..7
    const int tg   = lane & 3;       // 0..3
    const int wm   = wid & 3;        // warp m index 0..3
    const int wn   = wid >> 2;       // warp n index 0..1
    const int m0   = blockIdx.y * BM;
    const int n0   = blockIdx.x * BN;
    const int m0w  = wm * 32;
    const int n0w  = wn * 64;

    const float* Xb = X + (size_t)m0 * K;
    const float* Wb = W + (size_t)n0 * K;

    float D[2][8][4];
#pragma unroll
    for (int mi = 0; mi < 2; mi++)
#pragma unroll
        for (int ni = 0; ni < 8; ni++)
#pragma unroll
            for (int q = 0; q < 4; q++) D[mi][ni][q] = 0.f;

    // staging assignment: idx = l*256+tid; row = idx>>3 (0..127), col = (idx&7)*4
    float4 px[4], pw[4];
#pragma unroll
    for (int l = 0; l < 4; l++) {
        int idx = l * 256 + tid;
        int row = idx >> 3, col = (idx & 7) * 4;
        px[l] = *(const float4*)(Xb + (size_t)row * K + col);
        pw[l] = *(const float4*)(Wb + (size_t)row * K + col);
    }

    for (int k0 = 0; k0 < K; k0 += BK) {
#pragma unroll
        for (int l = 0; l < 4; l++) {
            int idx = l * 256 + tid;
            int row = idx >> 3, col = (idx & 7) * 4;
            Xs[row][col + 0] = f2tf32(px[l].x);
            Xs[row][col + 1] = f2tf32(px[l].y);
            Xs[row][col + 2] = f2tf32(px[l].z);
            Xs[row][col + 3] = f2tf32(px[l].w);
            Ws[row][col + 0] = f2tf32(pw[l].x);
            Ws[row][col + 1] = f2tf32(pw[l].y);
            Ws[row][col + 2] = f2tf32(pw[l].z);
            Ws[row][col + 3] = f2tf32(pw[l].w);
        }
        __syncthreads();

        if (k0 + BK < K) {
#pragma unroll
            for (int l = 0; l < 4; l++) {
                int idx = l * 256 + tid;
                int row = idx >> 3, col = (idx & 7) * 4;
                px[l] = *(const float4*)(Xb + (size_t)row * K + k0 + BK + col);
                pw[l] = *(const float4*)(Wb + (size_t)row * K + k0 + BK + col);
            }
        }

#pragma unroll
        for (int kk = 0; kk < BK; kk += 8) {
            unsigned a[2][4];
#pragma unroll
            for (int mi = 0; mi < 2; mi++) {
                a[mi][0] = Xs[m0w + mi * 16 + g][kk + tg];
                a[mi][1] = Xs[m0w + mi * 16 + 8 + g][kk + tg];
                a[mi][2] = Xs[m0w + mi * 16 + g][kk + tg + 4];
                a[mi][3] = Xs[m0w + mi * 16 + 8 + g][kk + tg + 4];
            }
#pragma unroll
            for (int ni = 0; ni < 8; ni++) {
                unsigned b0 = Ws[n0w + ni * 8 + g][kk + tg];
                unsigned b1 = Ws[n0w + ni * 8 + g][kk + tg + 4];
#pragma unroll
                for (int mi = 0; mi < 2; mi++) {
                    asm volatile(
                        "mma.sync.aligned.m16n8k8.row.col.f32.tf32.tf32.f32 "
                        "{%0,%1,%2,%3}, {%4,%5,%6,%7}, {%8,%9}, {%0,%1,%2,%3};"
                        : "+f"(D[mi][ni][0]), "+f"(D[mi][ni][1]),
                          "+f"(D[mi][ni][2]), "+f"(D[mi][ni][3])
                        : "r"(a[mi][0]), "r"(a[mi][1]), "r"(a[mi][2]), "r"(a[mi][3]),
                          "r"(b0), "r"(b1));
                }
            }
        }
        __syncthreads();
    }

    // epilogue: D frag (c0,c1)=(row g, cols 2tg,2tg+1), (c2,c3)=(row g+8, ...)
#pragma unroll
    for (int ni = 0; ni < 8; ni++) {
        int n = n0 + n0w + ni * 8 + 2 * tg;
        float bvx = bias[n], bvy = bias[n + 1];
#pragma unroll
        for (int mi = 0; mi < 2; mi++) {
            int mrow = m0 + m0w + mi * 16 + g;
            float2 o0 = make_float2(D[mi][ni][0] + bvx, D[mi][ni][1] + bvy);
            float2 o1 = make_float2(D[mi][ni][2] + bvx, D[mi][ni][3] + bvy);
            *(float2*)(out + (size_t)mrow * N + n)       = o0;
            *(float2*)(out + (size_t)(mrow + 8) * N + n) = o1;
        }
    }
}

// ============================================================================
// Persistent GRU recurrence (R3 version — best measured).
// 128 CTAs = 32 unit-tiles x 4 batch-tiles. 256 threads = 4 k-quarters x 64.
// Thread micro-tile: 4 batch x 2 units x 3 gates, packed f32x2 accumulators.
// ============================================================================
#define RBT 32
#define RUT 16
#define HP  516
#define KS4 128
#define RED_U64 (24 * 192)
#define REC_SMEM_BYTES ((RBT * HP + 48 * HP) * 4 + RED_U64 * 8)

__global__ __launch_bounds__(256)
void gru_rec(const float* __restrict__ xg,   // [B*T, 1536]
             const float* __restrict__ Whh,  // [1536, 512]
             const float* __restrict__ bhh,  // [1536]
             float* __restrict__ hseq,       // [B, T, 512]
             unsigned* __restrict__ ctr)
{
    extern __shared__ float sm[];
    float* h_s = sm;                                    // [RBT][HP]
    float* W_s = sm + RBT * HP;                         // [48][HP]
    unsigned long long* red =
        (unsigned long long*)(sm + RBT * HP + 48 * HP); // [24][192]
    __shared__ float bh_s[48];

    const int tid = threadIdx.x;
    const int u0  = blockIdx.x * RUT;
    const int b0  = blockIdx.y * RBT;
    const unsigned nCTA = gridDim.x * gridDim.y;

    for (int i = tid; i < 48 * (HID_ / 4); i += 256) {
        int rr = i >> 7;
        int c4 = i & 127;
        int g = rr >> 4, u = rr & 15;
        float4 v = *(const float4*)(Whh + (size_t)(g * HID_ + u0 + u) * HID_ + c4 * 4);
        *(float4*)&W_s[rr * HP + c4 * 4] = v;
    }
    if (tid < 48) {
        int g = tid >> 4, u = tid & 15;
        bh_s[tid] = bhh[g * HID_ + u0 + u];
    }

    const int ks  = tid >> 6;
    const int r   = tid & 63;
    const int ug2 = r & 7;
    const int bg  = r >> 3;
    const int kb  = ks * KS4;

    const ulonglong2* wp[2][3];
#pragma unroll
    for (int j = 0; j < 2; j++)
#pragma unroll
        for (int g = 0; g < 3; g++)
            wp[j][g] = (const ulonglong2*)(W_s + (g * 16 + ug2 + 8 * j) * HP + kb);
    const ulonglong2* hA = (const ulonglong2*)(h_s + (bg +  0) * HP + kb);
    const ulonglong2* hB = (const ulonglong2*)(h_s + (bg +  8) * HP + kb);
    const ulonglong2* hC = (const ulonglong2*)(h_s + (bg + 16) * HP + kb);
    const ulonglong2* hD = (const ulonglong2*)(h_s + (bg + 24) * HP + kb);

    for (int t = 0; t < T_; t++) {
        if (t == 0) {
            for (int i = tid; i < RBT * (HID_ / 4); i += 256)
                *(float4*)&h_s[(i >> 7) * HP + (i & 127) * 4] =
                    make_float4(0.f, 0.f, 0.f, 0.f);
        } else {
            for (int i = tid; i < RBT * (HID_ / 4); i += 256) {
                int rr = i >> 7, c4 = i & 127;
                const float* src = hseq + ((size_t)(b0 + rr) * T_ + (t - 1)) * HID_ + c4 * 4;
                unsigned sdst = (unsigned)__cvta_generic_to_shared(&h_s[rr * HP + c4 * 4]);
                asm volatile("cp.async.cg.shared.global [%0], [%1], 16;"
                             :: "r"(sdst), "l"(src));
            }
            asm volatile("cp.async.commit_group;");
        }

        float xv[2][3][4];
        if (ks == 0) {
#pragma unroll
            for (int i = 0; i < 4; i++) {
                size_t base = ((size_t)(b0 + bg + 8 * i) * T_ + t) * NG_ + u0;
#pragma unroll
                for (int j = 0; j < 2; j++) {
                    int u = ug2 + 8 * j;
                    xv[j][0][i] = __ldg(xg + base + u);
                    xv[j][1][i] = __ldg(xg + base + 512 + u);
                    xv[j][2][i] = __ldg(xg + base + 1024 + u);
                }
            }
        }

        if (t != 0) asm volatile("cp.async.wait_group 0;");
        __syncthreads();

        unsigned long long A[4][2][3];
#pragma unroll
        for (int i = 0; i < 4; i++)
#pragma unroll
            for (int j = 0; j < 2; j++)
#pragma unroll
                for (int g = 0; g < 3; g++) A[i][j][g] = 0ull;

#pragma unroll 4
        for (int k4 = 0; k4 < KS4 / 4; k4++) {
            ulonglong2 hv0 = hA[k4];
            ulonglong2 hv1 = hB[k4];
            ulonglong2 hv2 = hC[k4];
            ulonglong2 hv3 = hD[k4];
            ulonglong2 wv[2][3];
#pragma unroll
            for (int j = 0; j < 2; j++)
#pragma unroll
                for (int g = 0; g < 3; g++) wv[j][g] = wp[j][g][k4];

#pragma unroll
            for (int j = 0; j < 2; j++)
#pragma unroll
                for (int g = 0; g < 3; g++) {
                    A[0][j][g] = fma2(hv0.x, wv[j][g].x, A[0][j][g]);
                    A[0][j][g] = fma2(hv0.y, wv[j][g].y, A[0][j][g]);
                    A[1][j][g] = fma2(hv1.x, wv[j][g].x, A[1][j][g]);
                    A[1][j][g] = fma2(hv1.y, wv[j][g].y, A[1][j][g]);
                    A[2][j][g] = fma2(hv2.x, wv[j][g].x, A[2][j][g]);
                    A[2][j][g] = fma2(hv2.y, wv[j][g].y, A[2][j][g]);
                    A[3][j][g] = fma2(hv3.x, wv[j][g].x, A[3][j][g]);
                    A[3][j][g] = fma2(hv3.y, wv[j][g].y, A[3][j][g]);
                }
        }

        if (ks != 0) {
            int col = (ks - 1) * 64 + r;
#pragma unroll
            for (int i = 0; i < 4; i++)
#pragma unroll
                for (int j = 0; j < 2; j++)
#pragma unroll
                    for (int g = 0; g < 3; g++)
                        red[((i * 2 + j) * 3 + g) * 192 + col] = A[i][j][g];
        }
        __syncthreads();

        if (ks == 0) {
#pragma unroll
            for (int i = 0; i < 4; i++)
#pragma unroll
                for (int j = 0; j < 2; j++)
#pragma unroll
                    for (int g = 0; g < 3; g++) {
                        const unsigned long long* rp =
                            red + ((i * 2 + j) * 3 + g) * 192 + r;
                        A[i][j][g] = add2(A[i][j][g], rp[0]);
                        A[i][j][g] = add2(A[i][j][g], rp[64]);
                        A[i][j][g] = add2(A[i][j][g], rp[128]);
                    }

#pragma unroll
            for (int j = 0; j < 2; j++) {
                int ul = ug2 + 8 * j;
                const float br = bh_s[ul], bz = bh_s[16 + ul], bn = bh_s[32 + ul];
#pragma unroll
                for (int i = 0; i < 4; i++) {
                    float lo, hi;
                    unpack2(A[i][j][0], lo, hi); float hr = lo + hi + br;
                    unpack2(A[i][j][1], lo, hi); float hz = lo + hi + bz;
                    unpack2(A[i][j][2], lo, hi); float hn = lo + hi + bn;
                    float rr = 1.f / (1.f + __expf(-(xv[j][0][i] + hr)));
                    float zz = 1.f / (1.f + __expf(-(xv[j][1][i] + hz)));
                    float nn = tanhf(xv[j][2][i] + rr * hn);
                    float hp = h_s[(bg + 8 * i) * HP + u0 + ul];
                    int b = b0 + bg + 8 * i;
                    hseq[((size_t)b * T_ + t) * HID_ + u0 + ul] =
                        (1.f - zz) * nn + zz * hp;
                }
            }
        }
        __syncthreads();

        if (t < T_ - 1) {
            if (tid == 0) {
                __threadfence();
                atomicAdd(ctr, 1u);
                unsigned target = (unsigned)(t + 1) * nCTA;
                volatile unsigned* vc = ctr;
                while (*vc < target) { }
                __threadfence();
            }
            __syncthreads();
        }
    }
}

// ============================================================================
// Head
// ============================================================================
__global__ __launch_bounds__(64)
void out_proj(const float* __restrict__ hseq, const float* __restrict__ Wout,
              const float* __restrict__ bout, float* __restrict__ y)
{
    __shared__ float hs[HID_];
    const int b = blockIdx.x;
    const float* h = hseq + ((size_t)b * T_ + (T_ - 1)) * HID_;
    for (int i = threadIdx.x; i < HID_; i += 64) hs[i] = h[i];
    __syncthreads();

    const int o = threadIdx.x;
    float acc = bout[o];
    const float* w = Wout + (size_t)o * HID_;
#pragma unroll 4
    for (int k = 0; k < HID_; k += 4) {
        float4 wv = *(const float4*)(w + k);
        acc += hs[k] * wv.x + hs[k + 1] * wv.y + hs[k + 2] * wv.z + hs[k + 3] * wv.w;
    }
    y[b * OUT_ + o] = acc;
}

// ============================================================================
extern "C" void kernel_launch(void* const* d_in, const int* in_sizes, int n_in,
                              void* d_out, int out_size)
{
    (void)in_sizes; (void)n_in; (void)out_size;
    const float* x     = (const float*)d_in[0];
    const float* W_ih0 = (const float*)d_in[1];
    const float* W_hh0 = (const float*)d_in[2];
    const float* b_ih0 = (const float*)d_in[3];
    const float* b_hh0 = (const float*)d_in[4];
    const float* W_ih1 = (const float*)d_in[5];
    const float* W_hh1 = (const float*)d_in[6];
    const float* b_ih1 = (const float*)d_in[7];
    const float* b_hh1 = (const float*)d_in[8];
    const float* W_out = (const float*)d_in[9];
    const float* b_out = (const float*)d_in[10];
    float* y = (float*)d_out;

    float *xg, *h0, *h1;
    unsigned* ctr;
    cudaGetSymbolAddress((void**)&xg, g_xg);
    cudaGetSymbolAddress((void**)&h0, g_h0);
    cudaGetSymbolAddress((void**)&h1, g_h1);
    cudaGetSymbolAddress((void**)&ctr, g_ctr);

    cudaFuncSetAttribute(gru_rec, cudaFuncAttributeMaxDynamicSharedMemorySize,
                         REC_SMEM_BYTES);

    cudaMemsetAsync(ctr, 0, 2 * sizeof(unsigned));

    const dim3 ggrid(NG_ / BN, (B_ * T_) / BM);   // 12 x 256

    gemm_tf32<<<ggrid, 256>>>(x, W_ih0, b_ih0, xg, B_ * T_, NG_, IN_);
    gru_rec<<<dim3(HID_ / RUT, B_ / RBT), 256, REC_SMEM_BYTES>>>(xg, W_hh0, b_hh0, h0, ctr);

    gemm_tf32<<<ggrid, 256>>>(h0, W_ih1, b_ih1, xg, B_ * T_, NG_, HID_);
    gru_rec<<<dim3(HID_ / RUT, B_ / RBT), 256, REC_SMEM_BYTES>>>(xg, W_hh1, b_hh1, h1, ctr + 1);

    out_proj<<<B_, 64>>>(h1, W_out, b_out, y);
}